// round 8
// baseline (speedup 1.0000x reference)
#include <cuda_runtime.h>
#include <cuda_bf16.h>
#include <cstdint>

#define MAXN 100000
#define MAXE 1600000
#define E2CAP (MAXE + MAXN + 16)

// ---------------- device scratch (no allocations allowed) ----------------
__device__ float g_deg[MAXN];
__device__ float g_dinv[MAXN];
__device__ __align__(16) int   g_es[E2CAP];   // edge src (input order; self edges appended)
__device__ __align__(16) int   g_ed[E2CAP];   // edge dst
__device__ __align__(16) float g_en[E2CAP];   // edge norm
__device__ float2 g_p1[MAXN], g_p2[MAXN], g_p3[MAXN], g_p4[MAXN];
__device__ float  g_p5x[MAXN];
__device__ float  g_c[6 * 128];               // coef rows: c5, d4, d3, d2, d1, b5

// device-side state selection (host must NOT pass __device__ symbol addresses!)
__device__ __forceinline__ float2* state_ptr(int sel) {
    return (sel == 1) ? g_p1 : (sel == 2) ? g_p2 : (sel == 3) ? g_p3 : g_p4;
}

// ---------------- k1: deg = 1.0 (self loop weight) ----------------
__global__ void k_init(int n) {
    int i = blockIdx.x * blockDim.x + threadIdx.x;
    if (i < n) g_deg[i] = 1.0f;
}

// ---------------- k2: weighted degree (edge_index is int32 on device) ----------------
__global__ void k_deg(int ecnt, const int* __restrict__ ei, const float* __restrict__ ew) {
    int e = blockIdx.x * blockDim.x + threadIdx.x;
    if (e < ecnt) atomicAdd(&g_deg[ei[ecnt + e]], ew[e]);
}

// ---------------- coefficient chain (block 0 of k_node) ----------------
__device__ __forceinline__ void mv_row(const float* in, const float* W,
                                       int IN, int OUT, float* out, int j) {
    if (j < OUT) {
        float s = 0.0f;
        for (int k = 0; k < IN; k++) s += in[k] * W[k * OUT + j];
        out[j] = s;
    }
}

__device__ void weights_chain(const float* W1, const float* b1, const float* W2, const float* b2,
                              const float* W3, const float* b3, const float* W4, const float* b4,
                              const float* W5, const float* b5) {
    __shared__ float a[128], t[128];
    int j = threadIdx.x;

    if (j < 20) a[j] = W1[j];
    __syncthreads();
    mv_row(a, W2, 20, 40, t, j);  __syncthreads();
    mv_row(t, W3, 40, 60, a, j);  __syncthreads();
    mv_row(a, W4, 60, 80, t, j);  __syncthreads();
    mv_row(t, W5, 80, 100, &g_c[0 * 128], j); __syncthreads();

    if (j < 20) a[j] = b1[j];
    __syncthreads();
    mv_row(a, W2, 20, 40, t, j);  __syncthreads();
    mv_row(t, W3, 40, 60, a, j);  __syncthreads();
    mv_row(a, W4, 60, 80, t, j);  __syncthreads();
    mv_row(t, W5, 80, 100, &g_c[1 * 128], j); __syncthreads();

    if (j < 40) a[j] = b2[j];
    __syncthreads();
    mv_row(a, W3, 40, 60, t, j);  __syncthreads();
    mv_row(t, W4, 60, 80, a, j);  __syncthreads();
    mv_row(a, W5, 80, 100, &g_c[2 * 128], j); __syncthreads();

    if (j < 60) a[j] = b3[j];
    __syncthreads();
    mv_row(a, W4, 60, 80, t, j);  __syncthreads();
    mv_row(t, W5, 80, 100, &g_c[3 * 128], j); __syncthreads();

    if (j < 80) a[j] = b4[j];
    __syncthreads();
    mv_row(a, W5, 80, 100, &g_c[4 * 128], j); __syncthreads();

    if (j < 100) g_c[5 * 128 + j] = b5[j];
}

// ---------------- k3: dinv + p1 self seed + zero states + self edges + pads + coef chain ----------------
__global__ void k_node(int n, int ecnt, int e2p, const float* __restrict__ x,
                       const float* __restrict__ W1, const float* __restrict__ b1,
                       const float* __restrict__ W2, const float* __restrict__ b2,
                       const float* __restrict__ W3, const float* __restrict__ b3,
                       const float* __restrict__ W4, const float* __restrict__ b4,
                       const float* __restrict__ W5, const float* __restrict__ b5) {
    if (blockIdx.x == 0)
        weights_chain(W1, b1, W2, b2, W3, b3, W4, b4, W5, b5);

    int i = blockIdx.x * blockDim.x + threadIdx.x;
    if (i < n) {
        float di = rsqrtf(g_deg[i]);          // deg >= 1
        float sn = di * di;
        g_dinv[i] = di;
        g_p1[i] = make_float2(sn * __ldg(&x[i]), sn);   // pass-1 self contribution
        float2 z = make_float2(0.f, 0.f);
        g_p2[i] = z; g_p3[i] = z; g_p4[i] = z;
        g_p5x[i] = 0.0f;
        g_es[ecnt + i] = i;                   // self edge for passes 2..5
        g_ed[ecnt + i] = i;
        g_en[ecnt + i] = sn;
    } else if (i < n + 16) {                  // pad edges (norm = 0, harmless)
        int p = ecnt + i;
        if (p < e2p) { g_es[p] = 0; g_ed[p] = 0; g_en[p] = 0.0f; }
    }
}

// ---------------- k4: build edge arrays (coalesced, no sort) + fold in pass 1 ----------------
__global__ void k_build(int ecnt, const int* __restrict__ ei, const float* __restrict__ ew,
                        const float* __restrict__ x) {
    int e = (blockIdx.x * blockDim.x + threadIdx.x) * 4;
    if (e >= ecnt) return;
    if (e + 4 <= ecnt) {
        int4   s4 = *(const int4*)&ei[e];
        int4   d4 = *(const int4*)&ei[ecnt + e];
        float4 w4 = *(const float4*)&ew[e];
        float n0 = __ldg(&g_dinv[s4.x]) * w4.x * __ldg(&g_dinv[d4.x]);
        float n1 = __ldg(&g_dinv[s4.y]) * w4.y * __ldg(&g_dinv[d4.y]);
        float n2 = __ldg(&g_dinv[s4.z]) * w4.z * __ldg(&g_dinv[d4.z]);
        float n3 = __ldg(&g_dinv[s4.w]) * w4.w * __ldg(&g_dinv[d4.w]);
        *(int4*)&g_es[e] = s4;
        *(int4*)&g_ed[e] = d4;
        *(float4*)&g_en[e] = make_float4(n0, n1, n2, n3);
        float x0 = __ldg(&x[s4.x]), x1 = __ldg(&x[s4.y]);
        float x2 = __ldg(&x[s4.z]), x3 = __ldg(&x[s4.w]);
        atomicAdd(&g_p1[d4.x].x, n0 * x0); atomicAdd(&g_p1[d4.x].y, n0);
        atomicAdd(&g_p1[d4.y].x, n1 * x1); atomicAdd(&g_p1[d4.y].y, n1);
        atomicAdd(&g_p1[d4.z].x, n2 * x2); atomicAdd(&g_p1[d4.z].y, n2);
        atomicAdd(&g_p1[d4.w].x, n3 * x3); atomicAdd(&g_p1[d4.w].y, n3);
    } else {
        for (int q = e; q < ecnt; q++) {
            int s = ei[q], d = ei[ecnt + q];
            float nv = g_dinv[s] * ew[q] * g_dinv[d];
            g_es[q] = s; g_ed[q] = d; g_en[q] = nv;
            atomicAdd(&g_p1[d].x, nv * __ldg(&x[s]));
            atomicAdd(&g_p1[d].y, nv);
        }
    }
}

// ---------------- generic edge-parallel float2 pass: out[d] += n * in[s]  (8 edges/thread) ----------------
__global__ void k_epass(int e2p, int sel_in, int sel_out) {
    int t = (blockIdx.x * blockDim.x + threadIdx.x) * 8;
    if (t >= e2p) return;
    const float2* __restrict__ vin = state_ptr(sel_in);
    float2* vout = state_ptr(sel_out);
    int4   sA = *(const int4*)&g_es[t],     sB = *(const int4*)&g_es[t + 4];
    int4   dA = *(const int4*)&g_ed[t],     dB = *(const int4*)&g_ed[t + 4];
    float4 nA = *(const float4*)&g_en[t],   nB = *(const float4*)&g_en[t + 4];
    float2 w0 = __ldg(&vin[sA.x]);
    float2 w1 = __ldg(&vin[sA.y]);
    float2 w2 = __ldg(&vin[sA.z]);
    float2 w3 = __ldg(&vin[sA.w]);
    float2 w4 = __ldg(&vin[sB.x]);
    float2 w5 = __ldg(&vin[sB.y]);
    float2 w6 = __ldg(&vin[sB.z]);
    float2 w7 = __ldg(&vin[sB.w]);
    atomicAdd(&vout[dA.x].x, nA.x * w0.x); atomicAdd(&vout[dA.x].y, nA.x * w0.y);
    atomicAdd(&vout[dA.y].x, nA.y * w1.x); atomicAdd(&vout[dA.y].y, nA.y * w1.y);
    atomicAdd(&vout[dA.z].x, nA.z * w2.x); atomicAdd(&vout[dA.z].y, nA.z * w2.y);
    atomicAdd(&vout[dA.w].x, nA.w * w3.x); atomicAdd(&vout[dA.w].y, nA.w * w3.y);
    atomicAdd(&vout[dB.x].x, nB.x * w4.x); atomicAdd(&vout[dB.x].y, nB.x * w4.y);
    atomicAdd(&vout[dB.y].x, nB.y * w5.x); atomicAdd(&vout[dB.y].y, nB.y * w5.y);
    atomicAdd(&vout[dB.z].x, nB.z * w6.x); atomicAdd(&vout[dB.z].y, nB.z * w6.y);
    atomicAdd(&vout[dB.w].x, nB.w * w7.x); atomicAdd(&vout[dB.w].y, nB.w * w7.y);
}

// ---------------- pass 5: x-component only (p4 -> p5x) ----------------
__global__ void k_epass_x(int e2p) {
    int t = (blockIdx.x * blockDim.x + threadIdx.x) * 8;
    if (t >= e2p) return;
    const float2* __restrict__ vin = g_p4;
    int4   sA = *(const int4*)&g_es[t],     sB = *(const int4*)&g_es[t + 4];
    int4   dA = *(const int4*)&g_ed[t],     dB = *(const int4*)&g_ed[t + 4];
    float4 nA = *(const float4*)&g_en[t],   nB = *(const float4*)&g_en[t + 4];
    float v0 = __ldg(&vin[sA.x].x);
    float v1 = __ldg(&vin[sA.y].x);
    float v2 = __ldg(&vin[sA.z].x);
    float v3 = __ldg(&vin[sA.w].x);
    float v4 = __ldg(&vin[sB.x].x);
    float v5 = __ldg(&vin[sB.y].x);
    float v6 = __ldg(&vin[sB.z].x);
    float v7 = __ldg(&vin[sB.w].x);
    atomicAdd(&g_p5x[dA.x], nA.x * v0);
    atomicAdd(&g_p5x[dA.y], nA.y * v1);
    atomicAdd(&g_p5x[dA.z], nA.z * v2);
    atomicAdd(&g_p5x[dA.w], nA.w * v3);
    atomicAdd(&g_p5x[dB.x], nB.x * v4);
    atomicAdd(&g_p5x[dB.y], nB.y * v5);
    atomicAdd(&g_p5x[dB.z], nB.z * v6);
    atomicAdd(&g_p5x[dB.w], nB.w * v7);
}

// ---------------- final dense write-out ----------------
__global__ void k_final(int n, float* __restrict__ out) {
    __shared__ float sc[6][100];
    __shared__ float sv5[256], sa1[256], sa2[256], sa3[256], sa4[256];
    for (int t = threadIdx.x; t < 600; t += blockDim.x)
        sc[t / 100][t % 100] = g_c[(t / 100) * 128 + (t % 100)];

    int base = blockIdx.x * 256;
    int i = base + threadIdx.x;
    if (i < n) {
        sv5[threadIdx.x] = g_p5x[i];
        sa1[threadIdx.x] = g_p1[i].y;
        sa2[threadIdx.x] = g_p2[i].y;
        sa3[threadIdx.x] = g_p3[i].y;
        sa4[threadIdx.x] = g_p4[i].y;
    }
    __syncthreads();

    for (int t = threadIdx.x; t < 256 * 25; t += blockDim.x) {
        int wnode = t / 25;
        int ch = t - wnode * 25;
        int node = base + wnode;
        if (node >= n) break;
        float v5 = sv5[wnode];
        float a1 = sa1[wnode], a2 = sa2[wnode], a3 = sa3[wnode], a4 = sa4[wnode];
        int j0 = ch * 4;
        float4 r;
        float* rr = &r.x;
        #pragma unroll
        for (int q = 0; q < 4; q++) {
            int j = j0 + q;
            rr[q] = fmaxf(v5 * sc[0][j] + a4 * sc[1][j] + a3 * sc[2][j]
                        + a2 * sc[3][j] + a1 * sc[4][j] + sc[5][j], 0.0f);
        }
        ((float4*)(out + (size_t)node * 100))[ch] = r;
    }
}

// ---------------- launch ----------------
extern "C" void kernel_launch(void* const* d_in, const int* in_sizes, int n_in,
                              void* d_out, int out_size) {
    const float* x  = (const float*)d_in[0];
    const int*   ei = (const int*)d_in[1];     // int32! (JAX demotes int64)
    const float* ew = (const float*)d_in[2];
    const float* W1 = (const float*)d_in[3];  const float* b1 = (const float*)d_in[4];
    const float* W2 = (const float*)d_in[5];  const float* b2 = (const float*)d_in[6];
    const float* W3 = (const float*)d_in[7];  const float* b3 = (const float*)d_in[8];
    const float* W4 = (const float*)d_in[9];  const float* b4 = (const float*)d_in[10];
    const float* W5 = (const float*)d_in[11]; const float* b5 = (const float*)d_in[12];
    float* out = (float*)d_out;

    int n = in_sizes[0];
    int e = in_sizes[2];
    int e2p = (e + n + 7) & ~7;        // edges + self loops, padded to 8

    int tb = 256;
    int gbN  = (n + tb - 1) / tb;
    int gbE  = (e + tb - 1) / tb;
    int gbB  = ((e + 3) / 4 + tb - 1) / tb;      // build: 4 edges/thread
    int gbP  = (e2p / 8 + tb - 1) / tb;          // passes: 8 edges/thread

    k_init<<<gbN, tb>>>(n);
    k_deg<<<gbE, tb>>>(e, ei, ew);
    k_node<<<gbN, tb>>>(n, e, e2p, x, W1, b1, W2, b2, W3, b3, W4, b4, W5, b5);
    k_build<<<gbB, tb>>>(e, ei, ew, x);          // also computes p1

    k_epass<<<gbP, tb>>>(e2p, 1, 2);
    k_epass<<<gbP, tb>>>(e2p, 2, 3);
    k_epass<<<gbP, tb>>>(e2p, 3, 4);
    k_epass_x<<<gbP, tb>>>(e2p);
    k_final<<<gbN, tb>>>(n, out);

    (void)n_in; (void)out_size;
}

// round 9
// speedup vs baseline: 1.3497x; 1.3497x over previous
#include <cuda_runtime.h>
#include <cuda_bf16.h>
#include <cstdint>

#define MAXN 100000
#define MAXE 1600000
#define E2CAP (MAXE + MAXN + 16)
#define FPS 67108864.0f            // 2^26 fixed-point scale for weighted degree

// ---------------- device scratch (no allocations allowed) ----------------
__device__ unsigned long long g_pk[MAXN];   // packed: cnt<<46 | fixedpoint(weighted deg-1)
__device__ float g_dinv[MAXN];
__device__ int   g_off[MAXN + 1];
__device__ int   g_cur[MAXN];
__device__ int   g_bsums[128];
__device__ __align__(16) int2 g_csr[E2CAP];   // {src, __float_as_int(norm)}; row head = self edge
__device__ __align__(16) int  g_dsta[E2CAP];  // dst per edge (sorted ascending)
__device__ float2 g_p[5][MAXN];     // states 1..4: p[k] = (A^k x, A^k 1)
__device__ float  g_c[6 * 128];     // coef rows: c5, d4, d3, d2, d1, b5

// vector float2 atomic flush (sm_90+: single RED.64)
__device__ __forceinline__ void flush2(float2* addr, float ax, float ay) {
#if __CUDA_ARCH__ >= 900
    atomicAdd(addr, make_float2(ax, ay));
#else
    atomicAdd(&addr->x, ax);
    atomicAdd(&addr->y, ay);
#endif
}

// ---------------- preprocessing ----------------
__global__ void k_init(int n) {
    int i = blockIdx.x * blockDim.x + threadIdx.x;
    if (i < n) {
        g_pk[i] = 0ULL;
        float2 z = make_float2(0.f, 0.f);
        g_p[1][i] = z; g_p[2][i] = z; g_p[3][i] = z; g_p[4][i] = z;
    }
}

// edge_index is int32 on device (JAX x64-disabled demotes int64).
__global__ void k_edge_deg(int ecnt, const int* __restrict__ ei,
                           const float* __restrict__ ew) {
    int e = blockIdx.x * blockDim.x + threadIdx.x;
    if (e < ecnt) {
        int d = ei[ecnt + e];
        unsigned long long v = (unsigned long long)(ew[e] * FPS + 0.5f) | (1ULL << 46);
        atomicAdd(&g_pk[d], v);
    }
}

__global__ void k_scan1(int n) {
    __shared__ int sh[1024];
    int tid = threadIdx.x;
    int i = blockIdx.x * 1024 + tid;
    int v = (i < n) ? (int)(g_pk[i] >> 46) : 0;
    sh[tid] = v;
    __syncthreads();
    for (int off = 1; off < 1024; off <<= 1) {
        int t = (tid >= off) ? sh[tid - off] : 0;
        __syncthreads();
        sh[tid] += t;
        __syncthreads();
    }
    int incl = sh[tid];
    if (i < n) g_off[i] = incl - v;
    if (tid == 1023) g_bsums[blockIdx.x] = incl;
}

// Fused: bsums scan + final offsets (+i self slots) + dinv + self-edge emit + pads
__global__ void k_scan3f(int n, int nb, int e2) {
    __shared__ int sb[128];
    int tid = threadIdx.x;
    if (tid < 128) sb[tid] = (tid < nb) ? g_bsums[tid] : 0;
    __syncthreads();
    for (int off = 1; off < 128; off <<= 1) {
        int t = (tid >= off && tid < 128) ? sb[tid - off] : 0;
        __syncthreads();
        if (tid < 128) sb[tid] += t;
        __syncthreads();
    }
    if (blockIdx.x == 0) {
        if (tid == 0) g_off[n] = sb[nb - 1] + n;
        if (tid < 16) {                      // pad so edge kernels need no tail guard
            g_csr[e2 + tid] = make_int2(0, 0);   // norm = 0 -> contributes nothing
            g_dsta[e2 + tid] = n - 1;
        }
    }
    int i = blockIdx.x * blockDim.x + tid;
    if (i < n) {
        int blk = i >> 10;
        int o = g_off[i] + (blk ? sb[blk - 1] : 0) + i;   // +i: one self slot per prior node
        unsigned long long pk = g_pk[i];
        float deg = 1.0f + (float)(pk & ((1ULL << 46) - 1ULL)) * (1.0f / FPS);
        float di = rsqrtf(deg);
        g_dinv[i] = di;
        g_off[i] = o;
        g_cur[i] = o + 1;                                  // real edges start after self edge
        g_csr[o] = make_int2(i, __float_as_int(di * di));  // self edge, norm = dinv^2
        g_dsta[o] = i;
    }
}

__global__ void k_scatter(int ecnt, const int* __restrict__ ei,
                          const float* __restrict__ ew) {
    int e = blockIdx.x * blockDim.x + threadIdx.x;
    if (e < ecnt) {
        int s = ei[e];
        int d = ei[ecnt + e];
        int pos = atomicAdd(&g_cur[d], 1);
        float norm = g_dinv[s] * ew[e] * g_dinv[d];
        g_csr[pos] = make_int2(s, __float_as_int(norm));
        g_dsta[pos] = d;
    }
}

// ---------------- coefficient chain (device fn, run by block 0 of pass 1) ----------------
__device__ __forceinline__ void mv_row(const float* in, const float* W,
                                       int IN, int OUT, float* out, int j) {
    if (j < OUT) {
        float s = 0.0f;
        for (int k = 0; k < IN; k++) s += in[k] * W[k * OUT + j];
        out[j] = s;
    }
}

__device__ void weights_chain(const float* W1, const float* b1, const float* W2, const float* b2,
                              const float* W3, const float* b3, const float* W4, const float* b4,
                              const float* W5, const float* b5) {
    __shared__ float a[128], t[128];
    int j = threadIdx.x;

    if (j < 20) a[j] = W1[j];
    __syncthreads();
    mv_row(a, W2, 20, 40, t, j);  __syncthreads();
    mv_row(t, W3, 40, 60, a, j);  __syncthreads();
    mv_row(a, W4, 60, 80, t, j);  __syncthreads();
    mv_row(t, W5, 80, 100, &g_c[0 * 128], j); __syncthreads();

    if (j < 20) a[j] = b1[j];
    __syncthreads();
    mv_row(a, W2, 20, 40, t, j);  __syncthreads();
    mv_row(t, W3, 40, 60, a, j);  __syncthreads();
    mv_row(a, W4, 60, 80, t, j);  __syncthreads();
    mv_row(t, W5, 80, 100, &g_c[1 * 128], j); __syncthreads();

    if (j < 40) a[j] = b2[j];
    __syncthreads();
    mv_row(a, W3, 40, 60, t, j);  __syncthreads();
    mv_row(t, W4, 60, 80, a, j);  __syncthreads();
    mv_row(a, W5, 80, 100, &g_c[2 * 128], j); __syncthreads();

    if (j < 60) a[j] = b3[j];
    __syncthreads();
    mv_row(a, W4, 60, 80, t, j);  __syncthreads();
    mv_row(t, W5, 80, 100, &g_c[3 * 128], j); __syncthreads();

    if (j < 80) a[j] = b4[j];
    __syncthreads();
    mv_row(a, W5, 80, 100, &g_c[4 * 128], j); __syncthreads();

    if (j < 100) g_c[5 * 128 + j] = b5[j];
}

// ---------------- pass 1 (edge-parallel, 8 edges/thread, run-merged): p1 += {c*x[src], c} ----------------
__global__ void k_epass1(int e2, const float* __restrict__ x,
                         const float* __restrict__ W1, const float* __restrict__ b1,
                         const float* __restrict__ W2, const float* __restrict__ b2,
                         const float* __restrict__ W3, const float* __restrict__ b3,
                         const float* __restrict__ W4, const float* __restrict__ b4,
                         const float* __restrict__ W5, const float* __restrict__ b5) {
    if (blockIdx.x == 0)
        weights_chain(W1, b1, W2, b2, W3, b3, W4, b4, W5, b5);

    int t = (blockIdx.x * blockDim.x + threadIdx.x) * 8;
    if (t >= e2) return;
    int4 cA = *(const int4*)&g_csr[t];       // edges t, t+1
    int4 cB = *(const int4*)&g_csr[t + 2];
    int4 cC = *(const int4*)&g_csr[t + 4];
    int4 cD = *(const int4*)&g_csr[t + 6];
    int4 dA = *(const int4*)&g_dsta[t];
    int4 dB = *(const int4*)&g_dsta[t + 4];

    float c0 = __int_as_float(cA.y), c1 = __int_as_float(cA.w);
    float c2 = __int_as_float(cB.y), c3 = __int_as_float(cB.w);
    float c4 = __int_as_float(cC.y), c5 = __int_as_float(cC.w);
    float c6 = __int_as_float(cD.y), c7 = __int_as_float(cD.w);

    float vx[8];
    vx[0] = c0 * __ldg(&x[cA.x]);  vx[1] = c1 * __ldg(&x[cA.z]);
    vx[2] = c2 * __ldg(&x[cB.x]);  vx[3] = c3 * __ldg(&x[cB.z]);
    vx[4] = c4 * __ldg(&x[cC.x]);  vx[5] = c5 * __ldg(&x[cC.z]);
    vx[6] = c6 * __ldg(&x[cD.x]);  vx[7] = c7 * __ldg(&x[cD.z]);
    float vy[8] = {c0, c1, c2, c3, c4, c5, c6, c7};
    int ds[8] = {dA.x, dA.y, dA.z, dA.w, dB.x, dB.y, dB.z, dB.w};

    float2* out = g_p[1];
    float ax = vx[0], ay = vy[0];
    int cur = ds[0];
    #pragma unroll
    for (int q = 1; q < 8; q++) {
        if (ds[q] == cur) { ax += vx[q]; ay += vy[q]; }
        else { flush2(&out[cur], ax, ay); cur = ds[q]; ax = vx[q]; ay = vy[q]; }
    }
    flush2(&out[cur], ax, ay);
}

// ---------------- generic pass (edge-parallel, 8 edges/thread, run-merged) ----------------
__global__ void k_epass(int e2, int kin, int kout) {
    int t = (blockIdx.x * blockDim.x + threadIdx.x) * 8;
    if (t >= e2) return;
    const float2* __restrict__ vin = g_p[kin];
    int4 cA = *(const int4*)&g_csr[t];
    int4 cB = *(const int4*)&g_csr[t + 2];
    int4 cC = *(const int4*)&g_csr[t + 4];
    int4 cD = *(const int4*)&g_csr[t + 6];
    int4 dA = *(const int4*)&g_dsta[t];
    int4 dB = *(const int4*)&g_dsta[t + 4];

    float2 w0 = __ldg(&vin[cA.x]);
    float2 w1 = __ldg(&vin[cA.z]);
    float2 w2 = __ldg(&vin[cB.x]);
    float2 w3 = __ldg(&vin[cB.z]);
    float2 w4 = __ldg(&vin[cC.x]);
    float2 w5 = __ldg(&vin[cC.z]);
    float2 w6 = __ldg(&vin[cD.x]);
    float2 w7 = __ldg(&vin[cD.z]);

    float c0 = __int_as_float(cA.y), c1 = __int_as_float(cA.w);
    float c2 = __int_as_float(cB.y), c3 = __int_as_float(cB.w);
    float c4 = __int_as_float(cC.y), c5 = __int_as_float(cC.w);
    float c6 = __int_as_float(cD.y), c7 = __int_as_float(cD.w);

    float vx[8] = {c0 * w0.x, c1 * w1.x, c2 * w2.x, c3 * w3.x,
                   c4 * w4.x, c5 * w5.x, c6 * w6.x, c7 * w7.x};
    float vy[8] = {c0 * w0.y, c1 * w1.y, c2 * w2.y, c3 * w3.y,
                   c4 * w4.y, c5 * w5.y, c6 * w6.y, c7 * w7.y};
    int ds[8] = {dA.x, dA.y, dA.z, dA.w, dB.x, dB.y, dB.z, dB.w};

    float2* out = g_p[kout];
    float ax = vx[0], ay = vy[0];
    int cur = ds[0];
    #pragma unroll
    for (int q = 1; q < 8; q++) {
        if (ds[q] == cur) { ax += vx[q]; ay += vy[q]; }
        else { flush2(&out[cur], ax, ay); cur = ds[q]; ax = vx[q]; ay = vy[q]; }
    }
    flush2(&out[cur], ax, ay);
}

// ---------------- pass 5 (x-only, node-parallel pull; row includes self edge) + final write ----------------
__global__ void k_spmv5_final(int n, float* __restrict__ out) {
    __shared__ float sc[6][100];
    __shared__ float sv5[256], sa1[256], sa2[256], sa3[256], sa4[256];
    for (int t = threadIdx.x; t < 600; t += blockDim.x)
        sc[t / 100][t % 100] = g_c[(t / 100) * 128 + (t % 100)];

    int base = blockIdx.x * 256;
    int i = base + threadIdx.x;

    if (i < n) {
        const float2* __restrict__ vin = g_p[4];
        int e0 = g_off[i], e1 = g_off[i + 1];
        float ax = 0.0f;                         // self edge is in the row
        int e = e0;
        for (; e + 4 <= e1; e += 4) {
            int2 p0 = __ldg(&g_csr[e]);
            int2 p1 = __ldg(&g_csr[e + 1]);
            int2 p2 = __ldg(&g_csr[e + 2]);
            int2 p3 = __ldg(&g_csr[e + 3]);
            float v0 = __ldg(&vin[p0.x].x);
            float v1 = __ldg(&vin[p1.x].x);
            float v2 = __ldg(&vin[p2.x].x);
            float v3 = __ldg(&vin[p3.x].x);
            ax += __int_as_float(p0.y) * v0 + __int_as_float(p1.y) * v1
                + __int_as_float(p2.y) * v2 + __int_as_float(p3.y) * v3;
        }
        for (; e < e1; e++) {
            int2 p = __ldg(&g_csr[e]);
            ax += __int_as_float(p.y) * __ldg(&vin[p.x].x);
        }
        sv5[threadIdx.x] = ax;
        sa1[threadIdx.x] = g_p[1][i].y;
        sa2[threadIdx.x] = g_p[2][i].y;
        sa3[threadIdx.x] = g_p[3][i].y;
        sa4[threadIdx.x] = g_p[4][i].y;
    }
    __syncthreads();

    for (int t = threadIdx.x; t < 256 * 25; t += blockDim.x) {
        int wnode = t / 25;
        int ch = t - wnode * 25;
        int node = base + wnode;
        if (node >= n) break;
        float v5 = sv5[wnode];
        float a1 = sa1[wnode], a2 = sa2[wnode], a3 = sa3[wnode], a4 = sa4[wnode];
        int j0 = ch * 4;
        float4 r;
        float* rr = &r.x;
        #pragma unroll
        for (int q = 0; q < 4; q++) {
            int j = j0 + q;
            rr[q] = fmaxf(v5 * sc[0][j] + a4 * sc[1][j] + a3 * sc[2][j]
                        + a2 * sc[3][j] + a1 * sc[4][j] + sc[5][j], 0.0f);
        }
        ((float4*)(out + (size_t)node * 100))[ch] = r;
    }
}

// ---------------- launch ----------------
extern "C" void kernel_launch(void* const* d_in, const int* in_sizes, int n_in,
                              void* d_out, int out_size) {
    const float* x  = (const float*)d_in[0];
    const int*   ei = (const int*)d_in[1];     // int32! (JAX demotes int64)
    const float* ew = (const float*)d_in[2];
    const float* W1 = (const float*)d_in[3];  const float* b1 = (const float*)d_in[4];
    const float* W2 = (const float*)d_in[5];  const float* b2 = (const float*)d_in[6];
    const float* W3 = (const float*)d_in[7];  const float* b3 = (const float*)d_in[8];
    const float* W4 = (const float*)d_in[9];  const float* b4 = (const float*)d_in[10];
    const float* W5 = (const float*)d_in[11]; const float* b5 = (const float*)d_in[12];
    float* out = (float*)d_out;

    int n = in_sizes[0];
    int e = in_sizes[2];
    int e2 = e + n;                    // edges + self loops

    int tb = 256;
    int gbN  = (n + tb - 1) / tb;
    int gbE  = (e + tb - 1) / tb;
    int nb   = (n + 1023) / 1024;
    int tE   = (e2 + 7) / 8;           // one thread per 8 edges
    int gbE2 = (tE + tb - 1) / tb;

    k_init<<<gbN, tb>>>(n);
    k_edge_deg<<<gbE, tb>>>(e, ei, ew);
    k_scan1<<<nb, 1024>>>(n);
    k_scan3f<<<gbN, tb>>>(n, nb, e2);
    k_scatter<<<gbE, tb>>>(e, ei, ew);

    k_epass1<<<gbE2, tb>>>(e2, x, W1, b1, W2, b2, W3, b3, W4, b4, W5, b5);
    k_epass<<<gbE2, tb>>>(e2, 1, 2);
    k_epass<<<gbE2, tb>>>(e2, 2, 3);
    k_epass<<<gbE2, tb>>>(e2, 3, 4);
    k_spmv5_final<<<gbN, tb>>>(n, out);

    (void)n_in; (void)out_size;
}